// round 1
// baseline (speedup 1.0000x reference)
#include <cuda_runtime.h>
#include <math.h>
#include <float.h>

// Problem constants
#define Bb 4
#define Ss 4096
#define Ee 512
#define DKk 64
#define ROWS (Bb*Ss)          // 16384

// Scratch (device globals; no allocation allowed)
__device__ float g_Qt[Bb*DKk*Ss];   // [b][d][s]  (pre-scaled by 1/8)
__device__ float g_Kt[Bb*DKk*Ss];   // [b][d][s]
__device__ float g_V [Bb*Ss*DKk];   // [b][s][d]
__device__ unsigned char g_mask[ROWS];
__device__ int g_len[Bb];

// ---------------------------------------------------------------------------
// 1) mask[b,s] = any(x[b,s,:] != 0)
// ---------------------------------------------------------------------------
__global__ void mask_kernel(const float* __restrict__ x) {
    int warp = (blockIdx.x * blockDim.x + threadIdx.x) >> 5;
    int lane = threadIdx.x & 31;
    if (warp >= ROWS) return;
    const float4* row = (const float4*)(x + (size_t)warp * Ee);
    bool nz = false;
#pragma unroll
    for (int i = 0; i < 4; i++) {
        float4 v = row[lane + 32 * i];
        nz |= (v.x != 0.f) || (v.y != 0.f) || (v.z != 0.f) || (v.w != 0.f);
    }
    unsigned any = __ballot_sync(0xffffffffu, nz);
    if (lane == 0) g_mask[warp] = (any != 0u) ? 1 : 0;
}

// ---------------------------------------------------------------------------
// 2) Projections: C[row, :64] = A[row, :512] @ W, masked.
//    which=0: Q = x@Wq  -> g_Qt transposed, scaled by 0.125
//    which=1: K = ctx@Wk-> g_Kt transposed
//    which=2: V = ctx@Wv-> g_V  row-major
// ---------------------------------------------------------------------------
__global__ __launch_bounds__(256) void proj_kernel(
    const float* __restrict__ x, const float* __restrict__ ctx,
    const float* __restrict__ Wq, const float* __restrict__ Wk,
    const float* __restrict__ Wv)
{
    int which = blockIdx.y;
    const float* A = (which == 0) ? x : ctx;
    const float* W = (which == 0) ? Wq : ((which == 1) ? Wk : Wv);

    __shared__ float As[16][64];   // [kk][row]  (transposed A tile)
    __shared__ float Ws[16][64];   // [kk][col]

    int tid = threadIdx.x;
    int rb = blockIdx.x * 64;
    int tr = tid >> 4, tc = tid & 15;
    int r0 = tr * 4, c0 = tc * 4;

    float acc[4][4];
#pragma unroll
    for (int i = 0; i < 4; i++)
#pragma unroll
        for (int j = 0; j < 4; j++) acc[i][j] = 0.f;

    for (int kb = 0; kb < Ee; kb += 16) {
        {   // A tile: 64 rows x 16 k, store transposed
            int row = tid >> 2;
            int e4  = (tid & 3) * 4;
            float4 a = *(const float4*)(A + (size_t)(rb + row) * Ee + kb + e4);
            As[e4 + 0][row] = a.x; As[e4 + 1][row] = a.y;
            As[e4 + 2][row] = a.z; As[e4 + 3][row] = a.w;
        }
        {   // W tile: 16 k x 64 cols
            int kk = tid >> 4;
            int c4 = (tid & 15) * 4;
            *(float4*)&Ws[kk][c4] = *(const float4*)(W + (size_t)(kb + kk) * DKk + c4);
        }
        __syncthreads();
#pragma unroll
        for (int kk = 0; kk < 16; kk++) {
            float4 a = *(const float4*)&As[kk][r0];
            float4 w = *(const float4*)&Ws[kk][c0];
            acc[0][0] += a.x * w.x; acc[0][1] += a.x * w.y; acc[0][2] += a.x * w.z; acc[0][3] += a.x * w.w;
            acc[1][0] += a.y * w.x; acc[1][1] += a.y * w.y; acc[1][2] += a.y * w.z; acc[1][3] += a.y * w.w;
            acc[2][0] += a.z * w.x; acc[2][1] += a.z * w.y; acc[2][2] += a.z * w.z; acc[2][3] += a.z * w.w;
            acc[3][0] += a.w * w.x; acc[3][1] += a.w * w.y; acc[3][2] += a.w * w.z; acc[3][3] += a.w * w.w;
        }
        __syncthreads();
    }

    if (which == 2) {
#pragma unroll
        for (int i = 0; i < 4; i++) {
            int row = rb + r0 + i;
            float mv = (float)g_mask[row];
            float4 v;
            v.x = acc[i][0] * mv; v.y = acc[i][1] * mv;
            v.z = acc[i][2] * mv; v.w = acc[i][3] * mv;
            *(float4*)(g_V + (size_t)row * DKk + c0) = v;
        }
    } else {
        float* dst = (which == 0) ? g_Qt : g_Kt;
        float scale = (which == 0) ? 0.125f : 1.0f;   // 1/sqrt(64) folded into Q
#pragma unroll
        for (int i = 0; i < 4; i++) {
            int row = rb + r0 + i;
            int b = row >> 12;
            int s = row & (Ss - 1);
            float mv = (float)g_mask[row] * scale;
#pragma unroll
            for (int j = 0; j < 4; j++)
                dst[(size_t)b * DKk * Ss + (size_t)(c0 + j) * Ss + s] = acc[i][j] * mv;
        }
    }
}

// ---------------------------------------------------------------------------
// 3) lengths[b] = count_k( dot(Q[b,0,:], K[b,k,:]) != 0 )
//    (Q pre-scaled by 0.125: !=0 is invariant under nonzero scaling)
// ---------------------------------------------------------------------------
__global__ void len_kernel() {
    int b = blockIdx.x;
    __shared__ float qs[DKk];
    __shared__ int cnt;
    if (threadIdx.x == 0) cnt = 0;
    if (threadIdx.x < DKk)
        qs[threadIdx.x] = g_Qt[(size_t)b * DKk * Ss + (size_t)threadIdx.x * Ss + 0];
    __syncthreads();
    int c = 0;
    const float* Ktb = g_Kt + (size_t)b * DKk * Ss;
    for (int k = threadIdx.x; k < Ss; k += blockDim.x) {
        float dot = 0.f;
#pragma unroll
        for (int d = 0; d < DKk; d++) dot += qs[d] * Ktb[(size_t)d * Ss + k];
        c += (dot != 0.0f) ? 1 : 0;
    }
    atomicAdd(&cnt, c);
    __syncthreads();
    if (threadIdx.x == 0) g_len[b] = cnt;
}

// ---------------------------------------------------------------------------
// 4) Flash attention: out[b,q,:] = softmax(QK^T masked) @ V * mask
//    64 queries / block, 64-key tiles, online softmax.
//    smem: sQ [d][r], sKP shared K(d-major)/P(row-major), sV [k][d] = 48KB.
// ---------------------------------------------------------------------------
__global__ __launch_bounds__(256) void attn_kernel(float* __restrict__ out) {
    __shared__ float sQ [DKk * 64];  // [d][r]
    __shared__ float sKP[DKk * 64];  // phase 1: K [d][k]; phase 2: P [r][k]
    __shared__ float sV [64 * DKk];  // [k][d]

    int tid = threadIdx.x;
    int b  = blockIdx.x >> 6;
    int qb = (blockIdx.x & 63) * 64;
    int tr = tid >> 4, tc = tid & 15;
    int r0 = tr * 4, c0 = tc * 4;

    int len = g_len[b];
    const float* Qtb = g_Qt + (size_t)b * DKk * Ss;
    const float* Ktb = g_Kt + (size_t)b * DKk * Ss;
    const float* Vb  = g_V  + (size_t)b * Ss * DKk;

    // Load Q tile (d-major)
#pragma unroll
    for (int it = 0; it < 4; it++) {
        int idx = it * 256 + tid;        // float4 units
        int d  = idx >> 4;
        int r4 = (idx & 15) * 4;
        *(float4*)&sQ[d * 64 + r4] = *(const float4*)(Qtb + (size_t)d * Ss + qb + r4);
    }

    float o[4][4];
    float m[4], l[4];
#pragma unroll
    for (int i = 0; i < 4; i++) {
        m[i] = -INFINITY; l[i] = 0.f;
#pragma unroll
        for (int j = 0; j < 4; j++) o[i][j] = 0.f;
    }

    for (int kt = 0; kt < Ss / 64; kt++) {
        int kb = kt * 64;
        __syncthreads();   // prior PV reads of sKP/sV done
        // Load K tile (d-major) + V tile (row-major)
#pragma unroll
        for (int it = 0; it < 4; it++) {
            int idx = it * 256 + tid;
            int dk = idx >> 4;
            int c4 = (idx & 15) * 4;
            *(float4*)&sKP[dk * 64 + c4] = *(const float4*)(Ktb + (size_t)dk * Ss + kb + c4);
            *(float4*)&sV [dk * 64 + c4] = *(const float4*)(Vb + (size_t)(kb + dk) * DKk + c4);
        }
        __syncthreads();

        // s = Q^T K (Q already scaled by 1/8)
        float s[4][4];
#pragma unroll
        for (int i = 0; i < 4; i++)
#pragma unroll
            for (int j = 0; j < 4; j++) s[i][j] = 0.f;
#pragma unroll 8
        for (int d = 0; d < DKk; d++) {
            float4 qa = *(const float4*)&sQ [d * 64 + r0];
            float4 kv = *(const float4*)&sKP[d * 64 + c0];
            s[0][0] += qa.x * kv.x; s[0][1] += qa.x * kv.y; s[0][2] += qa.x * kv.z; s[0][3] += qa.x * kv.w;
            s[1][0] += qa.y * kv.x; s[1][1] += qa.y * kv.y; s[1][2] += qa.y * kv.z; s[1][3] += qa.y * kv.w;
            s[2][0] += qa.z * kv.x; s[2][1] += qa.z * kv.y; s[2][2] += qa.z * kv.z; s[2][3] += qa.z * kv.w;
            s[3][0] += qa.w * kv.x; s[3][1] += qa.w * kv.y; s[3][2] += qa.w * kv.z; s[3][3] += qa.w * kv.w;
        }

        // length mask (trailing padding)
        if (kb + 64 > len) {
#pragma unroll
            for (int j = 0; j < 4; j++) {
                if (kb + c0 + j >= len) {
#pragma unroll
                    for (int i = 0; i < 4; i++) s[i][j] = -INFINITY;
                }
            }
        }

        // row max across the 16 lanes that share the same 4 rows
        float pm[4];
#pragma unroll
        for (int i = 0; i < 4; i++)
            pm[i] = fmaxf(fmaxf(s[i][0], s[i][1]), fmaxf(s[i][2], s[i][3]));
#pragma unroll
        for (int off = 8; off >= 1; off >>= 1) {
#pragma unroll
            for (int i = 0; i < 4; i++)
                pm[i] = fmaxf(pm[i], __shfl_xor_sync(0xffffffffu, pm[i], off));
        }

        float f[4], ps[4];
#pragma unroll
        for (int i = 0; i < 4; i++) {
            float mn = fmaxf(m[i], pm[i]);
            f[i] = __expf(m[i] - mn);
            m[i] = mn;
#pragma unroll
            for (int j = 0; j < 4; j++) s[i][j] = __expf(s[i][j] - mn);
            ps[i] = s[i][0] + s[i][1] + s[i][2] + s[i][3];
        }
#pragma unroll
        for (int off = 8; off >= 1; off >>= 1) {
#pragma unroll
            for (int i = 0; i < 4; i++)
                ps[i] += __shfl_xor_sync(0xffffffffu, ps[i], off);
        }
#pragma unroll
        for (int i = 0; i < 4; i++) {
            l[i] = l[i] * f[i] + ps[i];
#pragma unroll
            for (int j = 0; j < 4; j++) o[i][j] *= f[i];
        }

        __syncthreads();   // all K reads of sKP done before storing P
#pragma unroll
        for (int i = 0; i < 4; i++) {
            float4 p4; p4.x = s[i][0]; p4.y = s[i][1]; p4.z = s[i][2]; p4.w = s[i][3];
            *(float4*)&sKP[(r0 + i) * 64 + c0] = p4;
        }
        __syncthreads();

        // o += P @ V
#pragma unroll
        for (int k4 = 0; k4 < 64; k4 += 4) {
            float pr[4][4];
#pragma unroll
            for (int i = 0; i < 4; i++) {
                float4 p4 = *(const float4*)&sKP[(r0 + i) * 64 + k4];
                pr[i][0] = p4.x; pr[i][1] = p4.y; pr[i][2] = p4.z; pr[i][3] = p4.w;
            }
#pragma unroll
            for (int u = 0; u < 4; u++) {
                float4 v = *(const float4*)&sV[(k4 + u) * 64 + c0];
#pragma unroll
                for (int i = 0; i < 4; i++) {
                    o[i][0] += pr[i][u] * v.x;
                    o[i][1] += pr[i][u] * v.y;
                    o[i][2] += pr[i][u] * v.z;
                    o[i][3] += pr[i][u] * v.w;
                }
            }
        }
    }

    // epilogue: out = (o / l) * mask
#pragma unroll
    for (int i = 0; i < 4; i++) {
        int row = b * Ss + qb + r0 + i;
        float scale = (float)g_mask[row] / l[i];
        float4 v;
        v.x = o[i][0] * scale; v.y = o[i][1] * scale;
        v.z = o[i][2] * scale; v.w = o[i][3] * scale;
        *(float4*)(out + (size_t)row * DKk + c0) = v;
    }
}

// ---------------------------------------------------------------------------
extern "C" void kernel_launch(void* const* d_in, const int* in_sizes, int n_in,
                              void* d_out, int out_size) {
    const float* x   = (const float*)d_in[0];
    const float* ctx = (const float*)d_in[1];
    const float* Wq  = (const float*)d_in[2];
    const float* Wk  = (const float*)d_in[3];
    const float* Wv  = (const float*)d_in[4];
    float* out = (float*)d_out;

    mask_kernel<<<ROWS / 8, 256>>>(x);
    proj_kernel<<<dim3(ROWS / 64, 3), 256>>>(x, ctx, Wq, Wk, Wv);
    len_kernel<<<Bb, 256>>>();
    attn_kernel<<<ROWS / 64, 256>>>(out);
}